// round 6
// baseline (speedup 1.0000x reference)
#include <cuda_runtime.h>
#include <math.h>

// ---------------- problem constants ----------------
#define B_ 256
#define T_ 36
#define S_ 96
#define D_ 1024
#define H_ 1024
#define L_ 2

static const long Y_SZ   = (long)B_*T_*D_;          // 9,437,184
static const long HID_SZ = (long)L_*B_*H_;          //   524,288
// attn region follows hidden in d_out

// ---------------- scratch layout (device global, no allocations) ------------
#define OFF_LOGITS 0L
#define OFF_XC     (OFF_LOGITS + (long)B_*S_)
#define OFF_GI0    (OFF_XC   + (long)B_*D_)
#define OFF_GH0    (OFF_GI0  + (long)B_*3*H_)
#define OFF_GI1    (OFF_GH0  + (long)B_*3*H_)
#define OFF_GH1    (OFF_GI1  + (long)B_*3*H_)
#define OFF_T1     (OFF_GH1  + (long)B_*3*H_)
#define OFF_YBUF   (OFF_T1   + (long)B_*D_)
#define N_ZERO     (OFF_YBUF + (long)B_*D_)          // everything before wenc is zeroed per step
#define OFF_WENC   N_ZERO
#define SC_TOTAL   (OFF_WENC + (long)B_*H_)

__device__ float g_scratch[SC_TOTAL];

// ---------------- zero kernel ----------------
__global__ void kzero4(float4* __restrict__ p, int n4) {
    int i = blockIdx.x * blockDim.x + threadIdx.x;
    int stride = gridDim.x * blockDim.x;
    float4 z = make_float4(0.f, 0.f, 0.f, 0.f);
    for (; i < n4; i += stride) p[i] = z;
}

// ---------------- split-K fp32 GEMM: C[m,n] += sum_k A[m,k]*W[n,k] ----------
// A is a virtual concat: k < K1 -> A1 (lda1), else A2 (lda2). M fixed = grid.y*64.
// Tile 64x64, 64 threads, 8x8 microtile, TK=16, register prefetch of next chunk.
// Atomic epilogue (C must be pre-zeroed; bias added by downstream kernels).
__device__ __forceinline__ float4 ldA4(const float* __restrict__ A1,
                                       const float* __restrict__ A2,
                                       int K1, int lda1, int lda2, int row, int k) {
    if (k < K1) return *reinterpret_cast<const float4*>(A1 + (long)row * lda1 + k);
    return *reinterpret_cast<const float4*>(A2 + (long)row * lda2 + (k - K1));
}

__global__ __launch_bounds__(64) void sgemm_atomic(
    const float* __restrict__ A1, const float* __restrict__ A2, int K1,
    int lda1, int lda2,
    const float* __restrict__ W, int ldw,
    float* __restrict__ C, int ldc,
    int N, int K, int Kslice)
{
    __shared__ float As[16][68];
    __shared__ float Bs[16][68];
    const int tid = threadIdx.x;
    const int tx = tid & 7, ty = tid >> 3;
    const int n0 = blockIdx.x * 64, m0 = blockIdx.y * 64;
    const int kstart = blockIdx.z * Kslice;
    const int kend = min(K, kstart + Kslice);
    const int nchunks = (kend - kstart) >> 4;

    const int lr  = tid >> 2;        // r = i*16 + lr
    const int lkq = (tid & 3) * 4;   // k sub-offset (float4)

    float acc[8][8];
#pragma unroll
    for (int i = 0; i < 8; i++)
#pragma unroll
        for (int j = 0; j < 8; j++) acc[i][j] = 0.f;

    float4 pa[4], pb[4];
    {
        int k0 = kstart;
#pragma unroll
        for (int i = 0; i < 4; i++) {
            int r = i * 16 + lr;
            pa[i] = ldA4(A1, A2, K1, lda1, lda2, m0 + r, k0 + lkq);
            int n = n0 + r;
            pb[i] = (n < N) ? *reinterpret_cast<const float4*>(W + (long)n * ldw + k0 + lkq)
                            : make_float4(0.f, 0.f, 0.f, 0.f);
        }
    }
    for (int c = 0; c < nchunks; c++) {
#pragma unroll
        for (int i = 0; i < 4; i++) {
            int r = i * 16 + lr;
            As[lkq + 0][r] = pa[i].x; As[lkq + 1][r] = pa[i].y;
            As[lkq + 2][r] = pa[i].z; As[lkq + 3][r] = pa[i].w;
            Bs[lkq + 0][r] = pb[i].x; Bs[lkq + 1][r] = pb[i].y;
            Bs[lkq + 2][r] = pb[i].z; Bs[lkq + 3][r] = pb[i].w;
        }
        __syncthreads();
        if (c + 1 < nchunks) {
            int k0 = kstart + (c + 1) * 16;
#pragma unroll
            for (int i = 0; i < 4; i++) {
                int r = i * 16 + lr;
                pa[i] = ldA4(A1, A2, K1, lda1, lda2, m0 + r, k0 + lkq);
                int n = n0 + r;
                pb[i] = (n < N) ? *reinterpret_cast<const float4*>(W + (long)n * ldw + k0 + lkq)
                                : make_float4(0.f, 0.f, 0.f, 0.f);
            }
        }
#pragma unroll
        for (int kk = 0; kk < 16; kk++) {
            float4 a0 = *reinterpret_cast<const float4*>(&As[kk][ty * 8]);
            float4 a1 = *reinterpret_cast<const float4*>(&As[kk][ty * 8 + 4]);
            float4 b0 = *reinterpret_cast<const float4*>(&Bs[kk][tx * 8]);
            float4 b1 = *reinterpret_cast<const float4*>(&Bs[kk][tx * 8 + 4]);
            float ar[8] = {a0.x, a0.y, a0.z, a0.w, a1.x, a1.y, a1.z, a1.w};
            float br[8] = {b0.x, b0.y, b0.z, b0.w, b1.x, b1.y, b1.z, b1.w};
#pragma unroll
            for (int i = 0; i < 8; i++)
#pragma unroll
                for (int j = 0; j < 8; j++)
                    acc[i][j] = fmaf(ar[i], br[j], acc[i][j]);
        }
        __syncthreads();
    }
    const int mb = m0 + ty * 8, nb = n0 + tx * 8;
#pragma unroll
    for (int i = 0; i < 8; i++) {
        float* crow = C + (long)(mb + i) * ldc + nb;
#pragma unroll
        for (int j = 0; j < 8; j++)
            if (nb + j < N) atomicAdd(crow + j, acc[i][j]);
    }
}

// ---------------- softmax over S=96 logits, writes attn output slice --------
__global__ void attn_softmax(const float* __restrict__ logits,
                             const float* __restrict__ bias,
                             float* __restrict__ outAttn, int t) {
    __shared__ float sv[S_];
    __shared__ float se[S_];
    int b = blockIdx.x, s = threadIdx.x;
    float v = logits[b * S_ + s] + bias[s];
    sv[s] = v;
    __syncthreads();
    float mx = -1e30f;
    for (int i = 0; i < S_; i++) mx = fmaxf(mx, sv[i]);
    float e = expf(v - mx);
    se[s] = e;
    __syncthreads();
    float sum = 0.f;
    for (int i = 0; i < S_; i++) sum += se[i];
    outAttn[((long)b * T_ + t) * S_ + s] = e / sum;
}

// ---------------- w_enc[b,:] = sum_s aw[b,s] * enc[b,s,:] -------------------
__global__ void weighted_enc(const float* __restrict__ outAttn, int t,
                             const float* __restrict__ enc,
                             float* __restrict__ wenc) {
    __shared__ float aw[S_];
    int b = blockIdx.x, tid = threadIdx.x;   // 256 threads, each owns 4 h via float4
    if (tid < S_) aw[tid] = outAttn[((long)b * T_ + t) * S_ + tid];
    __syncthreads();
    const float4* e = reinterpret_cast<const float4*>(enc + (long)b * S_ * H_);
    float4 acc = make_float4(0.f, 0.f, 0.f, 0.f);
#pragma unroll 4
    for (int s = 0; s < S_; s++) {
        float w = aw[s];
        float4 v = e[s * (H_ / 4) + tid];
        acc.x = fmaf(w, v.x, acc.x);
        acc.y = fmaf(w, v.y, acc.y);
        acc.z = fmaf(w, v.z, acc.z);
        acc.w = fmaf(w, v.w, acc.w);
    }
    reinterpret_cast<float4*>(wenc + (long)b * H_)[tid] = acc;
}

// ---------------- in-place bias (+ optional relu) ---------------------------
__global__ void bias_act(float* __restrict__ p, const float* __restrict__ b,
                         int cols, int relu) {
    long i = (long)blockIdx.x * blockDim.x + threadIdx.x;
    float v = p[i] + b[i % cols];
    if (relu) v = fmaxf(v, 0.f);
    p[i] = v;
}

// ---------------- GRU gate: h = (1-z)*n + z*h (in-place on h) --------------
__global__ void gru_gate(const float* __restrict__ gi, const float* __restrict__ gh,
                         const float* __restrict__ bi, const float* __restrict__ bh,
                         float* __restrict__ h) {
    int idx = blockIdx.x * blockDim.x + threadIdx.x;   // B*H
    int b = idx >> 10, j = idx & 1023;
    long base = (long)b * 3 * H_;
    float ir  = gi[base + j]          + bi[j];
    float iz  = gi[base + H_ + j]     + bi[H_ + j];
    float in_ = gi[base + 2 * H_ + j] + bi[2 * H_ + j];
    float hr  = gh[base + j]          + bh[j];
    float hz  = gh[base + H_ + j]     + bh[H_ + j];
    float hn  = gh[base + 2 * H_ + j] + bh[2 * H_ + j];
    float r = 1.f / (1.f + expf(-(ir + hr)));
    float z = 1.f / (1.f + expf(-(iz + hz)));
    float n = tanhf(in_ + r * hn);
    h[idx] = (1.f - z) * n + z * h[idx];
}

// ---------------- y slice writeback (+ out2 bias) ---------------------------
__global__ void copy_y(const float* __restrict__ ybuf, const float* __restrict__ b2,
                       float* __restrict__ outy, int t) {
    int idx = blockIdx.x * blockDim.x + threadIdx.x;   // B*D
    int b = idx >> 10, d = idx & 1023;
    outy[((long)b * T_ + t) * D_ + d] = ybuf[idx] + b2[d];
}

// ---------------- host driver ----------------
extern "C" void kernel_launch(void* const* d_in, const int* in_sizes, int n_in,
                              void* d_out, int out_size) {
    const float* target = (const float*)d_in[0];   // (B,T,D)
    const float* hidden0= (const float*)d_in[1];   // (L,B,H)
    const float* enc    = (const float*)d_in[2];   // (B,S,H)
    const float* attn_W = (const float*)d_in[3];   // (S, D+H)
    const float* attn_b = (const float*)d_in[4];
    const float* comb_W = (const float*)d_in[5];   // (D, D+H)
    const float* comb_b = (const float*)d_in[6];
    const float* W_ih   = (const float*)d_in[7];   // (L,3H,D)
    const float* W_hh   = (const float*)d_in[8];   // (L,3H,H)
    const float* b_ih   = (const float*)d_in[9];   // (L,3H)
    const float* b_hh   = (const float*)d_in[10];
    const float* out1_W = (const float*)d_in[11];  // (D,H)
    const float* out1_b = (const float*)d_in[12];
    const float* out2_W = (const float*)d_in[13];  // (D,D)
    const float* out2_b = (const float*)d_in[14];

    float* out     = (float*)d_out;
    float* outY    = out;                   // (B,T,D)
    float* hid     = out + Y_SZ;            // (L,B,H) — live recurrent state
    float* outAttn = out + Y_SZ + HID_SZ;   // (B,T,S)

    float* sc = nullptr;
    cudaGetSymbolAddress((void**)&sc, g_scratch);
    float* logits = sc + OFF_LOGITS;
    float* xc     = sc + OFF_XC;
    float* gi0    = sc + OFF_GI0;
    float* gh0    = sc + OFF_GH0;
    float* gi1    = sc + OFF_GI1;
    float* gh1    = sc + OFF_GH1;
    float* t1     = sc + OFF_T1;
    float* ybuf   = sc + OFF_YBUF;
    float* wenc   = sc + OFF_WENC;

    float* h0 = hid;
    float* h1 = hid + (long)B_ * H_;

    // initialize recurrent state from input hidden
    cudaMemcpyAsync(hid, hidden0, HID_SZ * sizeof(float),
                    cudaMemcpyDeviceToDevice, 0);

    for (int t = 0; t < T_; t++) {
        // zero all atomic-accumulated scratch for this step (~3.2 MB)
        kzero4<<<1024, 256>>>((float4*)sc, (int)(N_ZERO / 4));

        const float* x = target + (long)t * D_;   // row b at stride T*D

        // 1) attention logits: [x | h1] @ attn_W^T   (M=256, N=96, K=2048, splitK=16)
        {
            dim3 g((S_ + 63) / 64, B_ / 64, 16);
            sgemm_atomic<<<g, 64>>>(x, h1, D_, T_ * D_, H_,
                                    attn_W, D_ + H_, logits, S_, S_, D_ + H_, 128);
        }
        attn_softmax<<<B_, S_>>>(logits, attn_b, outAttn, t);
        weighted_enc<<<B_, H_ / 4>>>(outAttn, t, enc, wenc);

        // 2) combine: relu([x | w_enc] @ comb_W^T + b)   (N=1024, K=2048, splitK=4)
        {
            dim3 g(D_ / 64, B_ / 64, 4);
            sgemm_atomic<<<g, 64>>>(x, wenc, D_, T_ * D_, H_,
                                    comb_W, D_ + H_, xc, D_, D_, D_ + H_, 512);
        }
        bias_act<<<B_ * D_ / 256, 256>>>(xc, comb_b, D_, 1);

        // 3) GRU layer 0   (N=3072, K=1024, splitK=2)
        {
            dim3 g(3 * H_ / 64, B_ / 64, 2);
            sgemm_atomic<<<g, 64>>>(xc, xc, D_, D_, D_, W_ih, D_, gi0, 3 * H_,
                                    3 * H_, D_, 512);
            sgemm_atomic<<<g, 64>>>(h0, h0, H_, H_, H_, W_hh, H_, gh0, 3 * H_,
                                    3 * H_, H_, 512);
        }
        gru_gate<<<B_ * H_ / 256, 256>>>(gi0, gh0, b_ih, b_hh, h0);

        // 4) GRU layer 1
        {
            dim3 g(3 * H_ / 64, B_ / 64, 2);
            sgemm_atomic<<<g, 64>>>(h0, h0, H_, H_, H_, W_ih + (long)3 * H_ * D_,
                                    D_, gi1, 3 * H_, 3 * H_, D_, 512);
            sgemm_atomic<<<g, 64>>>(h1, h1, H_, H_, H_, W_hh + (long)3 * H_ * H_,
                                    H_, gh1, 3 * H_, 3 * H_, H_, 512);
        }
        gru_gate<<<B_ * H_ / 256, 256>>>(gi1, gh1, b_ih + 3 * H_, b_hh + 3 * H_, h1);

        // 5) output head: y = (h1 @ out1_W^T + b1) @ out2_W^T + b2
        {
            dim3 g(D_ / 64, B_ / 64, 4);
            sgemm_atomic<<<g, 64>>>(h1, h1, H_, H_, H_, out1_W, H_, t1, D_,
                                    D_, H_, 256);
        }
        bias_act<<<B_ * D_ / 256, 256>>>(t1, out1_b, D_, 0);
        {
            dim3 g(D_ / 64, B_ / 64, 4);
            sgemm_atomic<<<g, 64>>>(t1, t1, D_, D_, D_, out2_W, D_, ybuf, D_,
                                    D_, D_, 256);
        }
        copy_y<<<B_ * D_ / 256, 256>>>(ybuf, out2_b, outY, t);
    }
}